// round 3
// baseline (speedup 1.0000x reference)
#include <cuda_runtime.h>
#include <cuda_bf16.h>

#define B_    256
#define T_    192
#define E_    300
#define H_    128
#define G4    512
#define V_    11626
#define NT_   13
#define H2_   256
#define NEGV  (-10000.0f)
#define START_ 0
#define STOP_  10

// ---- device scratch (allocations are forbidden) ----
__device__ float g_proj[2][(size_t)V_ * G4];
__device__ float g_WhhT[2][H_ * G4];
__device__ float g_hbuf[(size_t)B_ * T_ * H2_];
__device__ float g_feats[(size_t)B_ * T_ * NT_];
__device__ float g_nll[B_];

__device__ __forceinline__ float sigf(float x) { return 1.f / (1.f + __expf(-x)); }
__device__ __forceinline__ float tanhfast(float x) { return 2.f / (1.f + __expf(-2.f * x)) - 1.f; }

__global__ void k_transpose_whh(const float* __restrict__ Wf, const float* __restrict__ Wb) {
    int d = blockIdx.y;
    const float* W = d ? Wb : Wf;
    int idx = blockIdx.x * blockDim.x + threadIdx.x;
    if (idx < H_ * G4) {
        int k = idx >> 9, g = idx & 511;
        g_WhhT[d][idx] = W[g * H_ + k];
    }
}

// proj[d][v][g] = sum_e emb[v][e] * W_ih[g][e] + b[g]
__global__ void __launch_bounds__(256) k_proj(const float* __restrict__ emb,
                       const float* __restrict__ Wf, const float* __restrict__ bf,
                       const float* __restrict__ Wb, const float* __restrict__ bb) {
    int d = blockIdx.z;
    const float* W    = d ? Wb : Wf;
    const float* bias = d ? bb : bf;
    __shared__ float As[16][65];
    __shared__ float Ws[16][65];
    int tid = threadIdx.x;
    int tx = tid & 15, ty = tid >> 4;
    int vm0 = blockIdx.x * 64;
    int gn0 = blockIdx.y * 64;
    float acc[4][4] = {};
    for (int k0 = 0; k0 < E_; k0 += 16) {
#pragma unroll
        for (int l = 0; l < 4; l++) {
            int lin = tid + l * 256;
            int m = lin >> 4, kk = lin & 15;
            int e = k0 + kk;
            int v = vm0 + m;
            As[kk][m] = (v < V_ && e < E_) ? emb[(size_t)v * E_ + e] : 0.f;
            int g = gn0 + m;
            Ws[kk][m] = (e < E_) ? W[(size_t)g * E_ + e] : 0.f;
        }
        __syncthreads();
#pragma unroll
        for (int kk = 0; kk < 16; kk++) {
            float a[4], w[4];
#pragma unroll
            for (int i = 0; i < 4; i++) a[i] = As[kk][ty * 4 + i];
#pragma unroll
            for (int j = 0; j < 4; j++) w[j] = Ws[kk][tx * 4 + j];
#pragma unroll
            for (int i = 0; i < 4; i++)
#pragma unroll
                for (int j = 0; j < 4; j++) acc[i][j] += a[i] * w[j];
        }
        __syncthreads();
    }
#pragma unroll
    for (int i = 0; i < 4; i++) {
        int v = vm0 + ty * 4 + i;
        if (v < V_) {
#pragma unroll
            for (int j = 0; j < 4; j++) {
                int g = gn0 + tx * 4 + j;
                g_proj[d][(size_t)v * G4 + g] = acc[i][j] + bias[g];
            }
        }
    }
}

// grid (64, 2): 4 batch rows per CTA, dir = blockIdx.y, 512 threads.
__global__ void __launch_bounds__(512) k_lstm(const int* __restrict__ sent,
                                              const int* __restrict__ seqlen) {
    const int d  = blockIdx.y;
    const int b0 = blockIdx.x * 4;
    __shared__ __align__(16) float h_s[4][128];
    __shared__ float4 gbuf4[512];
    __shared__ int toks[4][192];
    __shared__ int len_s[4];

    const int tid = threadIdx.x;
    const int g = tid;
    ((float*)h_s)[tid] = 0.f;
    for (int idx = tid; idx < 4 * T_; idx += 512) {
        int r = idx / T_, t = idx % T_;
        toks[r][t] = sent[(b0 + r) * T_ + t];
    }
    if (tid < 4) {
        int L = seqlen[b0 + tid];
        len_s[tid] = L < 1 ? 1 : (L > T_ ? T_ : L);
    }
    __syncthreads();

    int lenr[4];
#pragma unroll
    for (int r = 0; r < 4; r++) lenr[r] = len_s[r];

    const int pr = tid >> 7;
    const int pu = tid & 127;
    const int lenp = len_s[pr];
    float c_reg = 0.f;

    const float* __restrict__ proj = g_proj[d];
    const float* __restrict__ Wt   = g_WhhT[d];
    const size_t outbase = ((size_t)(b0 + pr) * T_) * H2_ + (size_t)d * H_ + pu;

    for (int t = 0; t < T_; t++) {
        float acc[4];
#pragma unroll
        for (int r = 0; r < 4; r++) {
            int L = lenr[r];
            bool m = t < L;
            int tt = (d == 0) ? t : (m ? (L - 1 - t) : t);
            int tok = toks[r][tt];
            acc[r] = __ldcg(&proj[(size_t)tok * G4 + g]);
        }
#pragma unroll 4
        for (int k4 = 0; k4 < 20; k4++) {       // k 0..79 via L1
            int kb = k4 * 4;
            float w0 = Wt[(kb + 0) * G4 + g];
            float w1 = Wt[(kb + 1) * G4 + g];
            float w2 = Wt[(kb + 2) * G4 + g];
            float w3 = Wt[(kb + 3) * G4 + g];
#pragma unroll
            for (int r = 0; r < 4; r++) {
                float4 hv = *(const float4*)&h_s[r][kb];
                acc[r] += w0 * hv.x + w1 * hv.y + w2 * hv.z + w3 * hv.w;
            }
        }
#pragma unroll 4
        for (int k4 = 20; k4 < 32; k4++) {      // k 80..127 L2-only
            int kb = k4 * 4;
            float w0 = __ldcg(&Wt[(kb + 0) * G4 + g]);
            float w1 = __ldcg(&Wt[(kb + 1) * G4 + g]);
            float w2 = __ldcg(&Wt[(kb + 2) * G4 + g]);
            float w3 = __ldcg(&Wt[(kb + 3) * G4 + g]);
#pragma unroll
            for (int r = 0; r < 4; r++) {
                float4 hv = *(const float4*)&h_s[r][kb];
                acc[r] += w0 * hv.x + w1 * hv.y + w2 * hv.z + w3 * hv.w;
            }
        }
        gbuf4[g] = make_float4(acc[0], acc[1], acc[2], acc[3]);
        __syncthreads();

        const float* gb = (const float*)gbuf4;
        float xi = gb[(pu)       * 4 + pr];
        float xf = gb[(pu + 128) * 4 + pr];
        float xg = gb[(pu + 256) * 4 + pr];
        float xo = gb[(pu + 384) * 4 + pr];
        float si = sigf(xi), sf = sigf(xf), so = sigf(xo);
        float tg = tanhfast(xg);
        float cn = sf * c_reg + si * tg;
        float hn = so * tanhfast(cn);
        bool m = t < lenp;
        float hold = h_s[pr][pu];
        c_reg = m ? cn : c_reg;
        float hkeep = m ? hn : hold;
        h_s[pr][pu] = hkeep;
        int outpos = (d == 0) ? t : (m ? (lenp - 1 - t) : t);
        float outv = m ? hn : 0.f;
        g_hbuf[outbase + (size_t)outpos * H2_] = outv;
        __syncthreads();
    }
}

__global__ void __launch_bounds__(256) k_fc(const float* __restrict__ Wfc, const float* __restrict__ bfc) {
    __shared__ float Wsh[NT_][260];
    __shared__ float bsh[NT_];
    int tid = threadIdx.x;
    for (int i = tid; i < NT_ * H2_; i += 256) Wsh[i / H2_][i % H2_] = Wfc[i];
    if (tid < NT_) bsh[tid] = bfc[tid];
    __syncthreads();
    int warp = tid >> 5, lane = tid & 31;
    size_t pos = (size_t)blockIdx.x * 8 + warp;
    const float* __restrict__ h = &g_hbuf[pos * H2_];
    if (lane < NT_) {
        float acc = bsh[lane];
        const float* wr = Wsh[lane];
#pragma unroll 8
        for (int k = 0; k < H2_; k++) acc += h[k] * wr[k];
        g_feats[pos * NT_ + lane] = acc;
    }
}

__global__ void __launch_bounds__(256) k_crf(const float* __restrict__ trans, const int* __restrict__ tags) {
    __shared__ float tr[NT_ * NT_];
    int tid = threadIdx.x;
    if (tid < NT_ * NT_) tr[tid] = trans[tid];
    __syncthreads();
    int warp = tid >> 5, lane = tid & 31;
    int b = blockIdx.x * 8 + warp;
    bool valid = lane < NT_;
    int jj = valid ? lane : 0;
    float alpha = valid ? ((jj == START_) ? 0.f : NEGV) : -1e30f;
    const float* __restrict__ fb = &g_feats[(size_t)b * T_ * NT_];

    for (int t = 0; t < T_; t++) {
        float m = -1e30f;
#pragma unroll
        for (int i = 0; i < NT_; i++) {
            float ai = __shfl_sync(0xffffffffu, alpha, i);
            m = fmaxf(m, ai + tr[jj * NT_ + i]);
        }
        float s = 0.f;
#pragma unroll
        for (int i = 0; i < NT_; i++) {
            float ai = __shfl_sync(0xffffffffu, alpha, i);
            s += __expf(ai + tr[jj * NT_ + i] - m);
        }
        float ft = fb[t * NT_ + jj];
        float an = m + __logf(s) + ft;
        if (valid) alpha = an;
    }
    float v = valid ? (alpha + tr[STOP_ * NT_ + jj]) : -1e30f;
    float mm = v;
#pragma unroll
    for (int off = 16; off; off >>= 1) mm = fmaxf(mm, __shfl_xor_sync(0xffffffffu, mm, off));
    float se = __expf(v - mm);
#pragma unroll
    for (int off = 16; off; off >>= 1) se += __shfl_xor_sync(0xffffffffu, se, off);
    float fwd = mm + __logf(se);

    float gold = 0.f;
    for (int t = lane; t < T_; t += 32) {
        int tg = tags[b * T_ + t];
        int tp = (t == 0) ? START_ : tags[b * T_ + t - 1];
        gold += tr[tg * NT_ + tp] + fb[t * NT_ + tg];
    }
#pragma unroll
    for (int off = 16; off; off >>= 1) gold += __shfl_xor_sync(0xffffffffu, gold, off);
    if (lane == 0) {
        int tlast = tags[b * T_ + T_ - 1];
        gold += tr[STOP_ * NT_ + tlast];
        g_nll[b] = fwd - gold;
    }
}

__global__ void k_reduce(float* __restrict__ out) {
    __shared__ float sm[256];
    int tid = threadIdx.x;
    sm[tid] = g_nll[tid];
    __syncthreads();
    for (int s = 128; s > 0; s >>= 1) {
        if (tid < s) sm[tid] += sm[tid + s];
        __syncthreads();
    }
    if (tid == 0) out[0] = sm[0] * (1.f / (float)B_);
}

extern "C" void kernel_launch(void* const* d_in, const int* in_sizes, int n_in,
                              void* d_out, int out_size) {
    const int*   sentence  = (const int*)d_in[0];
    const int*   seq_len   = (const int*)d_in[1];
    const int*   tags      = (const int*)d_in[2];
    const float* embedding = (const float*)d_in[3];
    const float* W_ih_f    = (const float*)d_in[4];
    const float* W_hh_f    = (const float*)d_in[5];
    const float* b_f       = (const float*)d_in[6];
    const float* W_ih_b    = (const float*)d_in[7];
    const float* W_hh_b    = (const float*)d_in[8];
    const float* b_b       = (const float*)d_in[9];
    const float* W_fc      = (const float*)d_in[10];
    const float* b_fc      = (const float*)d_in[11];
    const float* trans     = (const float*)d_in[12];

    dim3 gt((H_ * G4 + 255) / 256, 2);
    k_transpose_whh<<<gt, 256>>>(W_hh_f, W_hh_b);
    dim3 gp((V_ + 63) / 64, (G4 + 63) / 64, 2);
    k_proj<<<gp, 256>>>(embedding, W_ih_f, b_f, W_ih_b, b_b);
    dim3 gl(B_ / 4, 2);
    k_lstm<<<gl, 512>>>(sentence, seq_len);
    k_fc<<<(B_ * T_) / 8, 256>>>(W_fc, b_fc);
    k_crf<<<B_ / 8, 256>>>(trans, tags);
    k_reduce<<<1, 256>>>((float*)d_out);
}

// round 4
// speedup vs baseline: 1.3400x; 1.3400x over previous
#include <cuda_runtime.h>
#include <cuda_bf16.h>

#define B_    256
#define T_    192
#define E_    300
#define H_    128
#define G4    512
#define V_    11626
#define NT_   13
#define H2_   256
#define NEGV  (-10000.0f)
#define START_ 0
#define STOP_  10

typedef unsigned long long ull;

// ---- device scratch (allocations are forbidden) ----
__device__ float g_proj[2][(size_t)V_ * G4];
__device__ ull   g_Wpbf[2][32 * G4];            // [k4][g] 4 bf16 packed
__device__ float g_hbuf[(size_t)B_ * T_ * H2_];
__device__ float g_feats[(size_t)B_ * T_ * NT_];
__device__ float g_nll[B_];

__device__ __forceinline__ float sigf(float x) { return 1.f / (1.f + __expf(-x)); }
__device__ __forceinline__ float tanhfast(float x) { return 2.f / (1.f + __expf(-2.f * x)) - 1.f; }

__device__ __forceinline__ void fma2(ull& acc, ull a, ull b) {
    asm("fma.rn.f32x2 %0, %1, %2, %0;" : "+l"(acc) : "l"(a), "l"(b));
}
__device__ __forceinline__ ull dupf(float a) {
    ull r; asm("mov.b64 %0, {%1, %1};" : "=l"(r) : "f"(a)); return r;
}
__device__ __forceinline__ float unpack_sum(ull a) {
    float lo, hi; asm("mov.b64 {%0, %1}, %2;" : "=f"(lo), "=f"(hi) : "l"(a)); return lo + hi;
}
__device__ __forceinline__ void unpack2(ull a, float& lo, float& hi) {
    asm("mov.b64 {%0, %1}, %2;" : "=f"(lo), "=f"(hi) : "l"(a));
}
__device__ __forceinline__ void lds_v2(unsigned addr, ull& x, ull& y) {
    asm("ld.shared.v2.u64 {%0, %1}, [%2];" : "=l"(x), "=l"(y) : "r"(addr));
}
__device__ __forceinline__ void expand_bf4(ull w, ull& p01, ull& p23) {
    unsigned lo = (unsigned)w, hi = (unsigned)(w >> 32);
    unsigned f0 = lo << 16, f1 = lo & 0xFFFF0000u;
    unsigned f2 = hi << 16, f3 = hi & 0xFFFF0000u;
    asm("mov.b64 %0, {%1, %2};" : "=l"(p01) : "r"(f0), "r"(f1));
    asm("mov.b64 %0, {%1, %2};" : "=l"(p23) : "r"(f2), "r"(f3));
}

// ---- pack W_hh -> bf16x4 [k4][g] ----
__global__ void k_pack(const float* __restrict__ Wf, const float* __restrict__ Wb) {
    int d = blockIdx.y;
    const float* W = d ? Wb : Wf;
    int idx = blockIdx.x * 256 + threadIdx.x;   // over 32*512
    if (idx < 32 * G4) {
        int k4 = idx >> 9, g = idx & 511;
        ull out = 0;
#pragma unroll
        for (int j = 0; j < 4; j++) {
            __nv_bfloat16 b = __float2bfloat16(W[g * H_ + k4 * 4 + j]);
            unsigned short bits = *(unsigned short*)&b;
            out |= (ull)bits << (16 * j);
        }
        g_Wpbf[d][idx] = out;
    }
}

// ---- proj[d][v][g] = emb[v]·W_ih[g] + b[g], 128x128 tiles, FFMA2 ----
__global__ void __launch_bounds__(256) k_proj(const float* __restrict__ emb,
                       const float* __restrict__ Wf, const float* __restrict__ bf,
                       const float* __restrict__ Wb, const float* __restrict__ bb) {
    int d = blockIdx.z;
    const float* W    = d ? Wb : Wf;
    const float* bias = d ? bb : bf;
    __shared__ __align__(16) float As[8][128];
    __shared__ __align__(16) float Ws[8][128];
    int tid = threadIdx.x;
    int tx = tid & 15, ty = tid >> 4;
    int vm0 = blockIdx.x * 128;
    int gn0 = blockIdx.y * 128;
    int sm = tid & 127, skg = tid >> 7;

    ull acc2[8][4];
#pragma unroll
    for (int i = 0; i < 8; i++)
#pragma unroll
        for (int j = 0; j < 4; j++) acc2[i][j] = 0ull;

    unsigned wsb = (unsigned)__cvta_generic_to_shared(&Ws[0][0]) + tx * 32;

    for (int k0 = 0; k0 < 304; k0 += 8) {
        int e = k0 + skg * 4;
        int v = vm0 + sm;
        float4 av = make_float4(0.f, 0.f, 0.f, 0.f);
        if (v < V_ && e < E_) av = *(const float4*)&emb[(size_t)v * E_ + e];
        As[skg * 4 + 0][sm] = av.x;
        As[skg * 4 + 1][sm] = av.y;
        As[skg * 4 + 2][sm] = av.z;
        As[skg * 4 + 3][sm] = av.w;
        float4 wv = make_float4(0.f, 0.f, 0.f, 0.f);
        if (e < E_) wv = *(const float4*)&W[(size_t)(gn0 + sm) * E_ + e];
        Ws[skg * 4 + 0][sm] = wv.x;
        Ws[skg * 4 + 1][sm] = wv.y;
        Ws[skg * 4 + 2][sm] = wv.z;
        Ws[skg * 4 + 3][sm] = wv.w;
        __syncthreads();
#pragma unroll
        for (int kk = 0; kk < 8; kk++) {
            float4 a0 = *(const float4*)&As[kk][ty * 8];
            float4 a1 = *(const float4*)&As[kk][ty * 8 + 4];
            ull w01, w23, w45, w67;
            lds_v2(wsb + kk * 512, w01, w23);
            lds_v2(wsb + kk * 512 + 16, w45, w67);
            float aa[8] = {a0.x, a0.y, a0.z, a0.w, a1.x, a1.y, a1.z, a1.w};
#pragma unroll
            for (int i = 0; i < 8; i++) {
                ull ai = dupf(aa[i]);
                fma2(acc2[i][0], ai, w01);
                fma2(acc2[i][1], ai, w23);
                fma2(acc2[i][2], ai, w45);
                fma2(acc2[i][3], ai, w67);
            }
        }
        __syncthreads();
    }
    float bv[8];
    {
        float4 b0 = *(const float4*)&bias[gn0 + tx * 8];
        float4 b1 = *(const float4*)&bias[gn0 + tx * 8 + 4];
        bv[0] = b0.x; bv[1] = b0.y; bv[2] = b0.z; bv[3] = b0.w;
        bv[4] = b1.x; bv[5] = b1.y; bv[6] = b1.z; bv[7] = b1.w;
    }
#pragma unroll
    for (int i = 0; i < 8; i++) {
        int v = vm0 + ty * 8 + i;
        if (v < V_) {
            float c[8];
#pragma unroll
            for (int j = 0; j < 4; j++) unpack2(acc2[i][j], c[2 * j], c[2 * j + 1]);
            float* dst = &g_proj[d][(size_t)v * G4 + gn0 + tx * 8];
            *(float4*)dst = make_float4(c[0] + bv[0], c[1] + bv[1], c[2] + bv[2], c[3] + bv[3]);
            *(float4*)(dst + 4) = make_float4(c[4] + bv[4], c[5] + bv[5], c[6] + bv[6], c[7] + bv[7]);
        }
    }
}

// ---- BiLSTM recurrence: grid (64,2), 256 threads, 2 gates/thread ----
__global__ void __launch_bounds__(256) k_lstm(const int* __restrict__ sent,
                                              const int* __restrict__ seqlen) {
    const int d  = blockIdx.y;
    const int b0 = blockIdx.x * 4;
    __shared__ __align__(16) float h_s[4][128];
    __shared__ float4 gbuf4[512];
    __shared__ int toks[4][192];
    __shared__ int len_s[4];

    const int tid = threadIdx.x;
    ((float*)h_s)[tid] = 0.f;
    ((float*)h_s)[tid + 256] = 0.f;
    for (int idx = tid; idx < 4 * T_; idx += 256) {
        int r = idx / T_, t = idx % T_;
        toks[r][t] = sent[(b0 + r) * T_ + t];
    }
    if (tid < 4) {
        int L = seqlen[b0 + tid];
        len_s[tid] = L < 1 ? 1 : (L > T_ ? T_ : L);
    }
    __syncthreads();

    int lenr[4];
#pragma unroll
    for (int r = 0; r < 4; r++) lenr[r] = len_s[r];

    const int gA = tid, gB = tid + 256;
    const int pr0 = (tid >> 7) << 1;       // 0 or 2
    const int pu = tid & 127;
    const int len0 = len_s[pr0];
    const int len1 = len_s[pr0 + 1];
    float c0 = 0.f, c1 = 0.f;

    const float* __restrict__ proj = g_proj[d];
    const ull* __restrict__ WpA = g_Wpbf[d] + gA;
    const ull* __restrict__ WpB = g_Wpbf[d] + gB;
    const size_t ob0 = ((size_t)(b0 + pr0) * T_) * H2_ + (size_t)d * H_ + pu;
    const size_t ob1 = ob0 + (size_t)T_ * H2_;
    const unsigned hb = (unsigned)__cvta_generic_to_shared(&h_s[0][0]);

    for (int t = 0; t < T_; t++) {
        float pa[4], pb[4];
#pragma unroll
        for (int r = 0; r < 4; r++) {
            int L = lenr[r];
            bool m = t < L;
            int tt = (d == 0) ? t : (m ? (L - 1 - t) : t);
            int tok = toks[r][tt];
            const float* p = proj + (size_t)tok * G4;
            pa[r] = __ldcg(p + gA);
            pb[r] = __ldcg(p + gB);
        }
        ull aA0 = 0, aA1 = 0, aA2 = 0, aA3 = 0;
        ull aB0 = 0, aB1 = 0, aB2 = 0, aB3 = 0;
#pragma unroll 4
        for (int k4 = 0; k4 < 32; k4++) {
            ull wa = WpA[k4 * G4];
            ull wb = WpB[k4 * G4];
            ull wa01, wa23, wb01, wb23;
            expand_bf4(wa, wa01, wa23);
            expand_bf4(wb, wb01, wb23);
            unsigned ha = hb + k4 * 16;
            ull h01, h23;
            lds_v2(ha, h01, h23);
            fma2(aA0, h01, wa01); fma2(aA0, h23, wa23);
            fma2(aB0, h01, wb01); fma2(aB0, h23, wb23);
            lds_v2(ha + 512, h01, h23);
            fma2(aA1, h01, wa01); fma2(aA1, h23, wa23);
            fma2(aB1, h01, wb01); fma2(aB1, h23, wb23);
            lds_v2(ha + 1024, h01, h23);
            fma2(aA2, h01, wa01); fma2(aA2, h23, wa23);
            fma2(aB2, h01, wb01); fma2(aB2, h23, wb23);
            lds_v2(ha + 1536, h01, h23);
            fma2(aA3, h01, wa01); fma2(aA3, h23, wa23);
            fma2(aB3, h01, wb01); fma2(aB3, h23, wb23);
        }
        gbuf4[gA] = make_float4(pa[0] + unpack_sum(aA0), pa[1] + unpack_sum(aA1),
                                pa[2] + unpack_sum(aA2), pa[3] + unpack_sum(aA3));
        gbuf4[gB] = make_float4(pb[0] + unpack_sum(aB0), pb[1] + unpack_sum(aB1),
                                pb[2] + unpack_sum(aB2), pb[3] + unpack_sum(aB3));
        __syncthreads();

        const float* gb = (const float*)gbuf4;
        // row pr0
        {
            float xi = gb[pu * 4 + pr0];
            float xf = gb[(pu + 128) * 4 + pr0];
            float xg = gb[(pu + 256) * 4 + pr0];
            float xo = gb[(pu + 384) * 4 + pr0];
            float si = sigf(xi), sf = sigf(xf), so = sigf(xo);
            float tg = tanhfast(xg);
            float cn = sf * c0 + si * tg;
            float hn = so * tanhfast(cn);
            bool m = t < len0;
            float hold = h_s[pr0][pu];
            c0 = m ? cn : c0;
            h_s[pr0][pu] = m ? hn : hold;
            int outpos = (d == 0) ? t : (m ? (len0 - 1 - t) : t);
            g_hbuf[ob0 + (size_t)outpos * H2_] = m ? hn : 0.f;
        }
        // row pr0+1
        {
            float xi = gb[pu * 4 + pr0 + 1];
            float xf = gb[(pu + 128) * 4 + pr0 + 1];
            float xg = gb[(pu + 256) * 4 + pr0 + 1];
            float xo = gb[(pu + 384) * 4 + pr0 + 1];
            float si = sigf(xi), sf = sigf(xf), so = sigf(xo);
            float tg = tanhfast(xg);
            float cn = sf * c1 + si * tg;
            float hn = so * tanhfast(cn);
            bool m = t < len1;
            float hold = h_s[pr0 + 1][pu];
            c1 = m ? cn : c1;
            h_s[pr0 + 1][pu] = m ? hn : hold;
            int outpos = (d == 0) ? t : (m ? (len1 - 1 - t) : t);
            g_hbuf[ob1 + (size_t)outpos * H2_] = m ? hn : 0.f;
        }
        __syncthreads();
    }
}

// ---- FC: warp per position, float4 ----
__global__ void __launch_bounds__(256) k_fc(const float* __restrict__ Wfc, const float* __restrict__ bfc) {
    __shared__ float4 Wsh4[NT_][65];
    __shared__ float bsh[16];
    int tid = threadIdx.x;
    for (int i = tid; i < NT_ * 64; i += 256) {
        int j = i >> 6, k4 = i & 63;
        Wsh4[j][k4] = ((const float4*)Wfc)[j * 64 + k4];
    }
    if (tid < NT_) bsh[tid] = bfc[tid];
    __syncthreads();
    int warp = tid >> 5, lane = tid & 31;
    size_t pos = (size_t)blockIdx.x * 8 + warp;
    const float4* __restrict__ h4p = (const float4*)&g_hbuf[pos * H2_];
    if (lane < NT_) {
        float acc0 = bsh[lane], acc1 = 0.f;
#pragma unroll 8
        for (int k4 = 0; k4 < 64; k4++) {
            float4 h = h4p[k4];
            float4 w = Wsh4[lane][k4];
            acc0 = fmaf(h.x, w.x, acc0);
            acc1 = fmaf(h.y, w.y, acc1);
            acc0 = fmaf(h.z, w.z, acc0);
            acc1 = fmaf(h.w, w.w, acc1);
        }
        g_feats[pos * NT_ + lane] = acc0 + acc1;
    }
}

// ---- CRF ----
__global__ void __launch_bounds__(256) k_crf(const float* __restrict__ trans, const int* __restrict__ tags) {
    __shared__ float tr[NT_ * NT_];
    int tid = threadIdx.x;
    if (tid < NT_ * NT_) tr[tid] = trans[tid];
    __syncthreads();
    int warp = tid >> 5, lane = tid & 31;
    int b = blockIdx.x * 8 + warp;
    bool valid = lane < NT_;
    int jj = valid ? lane : 0;
    float trr[NT_];
#pragma unroll
    for (int i = 0; i < NT_; i++) trr[i] = tr[jj * NT_ + i];
    float alpha = valid ? ((jj == START_) ? 0.f : NEGV) : -1e30f;
    const float* __restrict__ fb = &g_feats[(size_t)b * T_ * NT_];

    for (int t = 0; t < T_; t++) {
        float ft = valid ? fb[t * NT_ + jj] : 0.f;
        float v[NT_];
#pragma unroll
        for (int i = 0; i < NT_; i++)
            v[i] = __shfl_sync(0xffffffffu, alpha, i) + trr[i];
        float m0 = fmaxf(v[0], v[1]),  m1 = fmaxf(v[2], v[3]);
        float m2 = fmaxf(v[4], v[5]),  m3 = fmaxf(v[6], v[7]);
        float m4 = fmaxf(v[8], v[9]),  m5 = fmaxf(v[10], v[11]);
        m0 = fmaxf(m0, m1); m2 = fmaxf(m2, m3); m4 = fmaxf(m4, fmaxf(m5, v[12]));
        float m = fmaxf(fmaxf(m0, m2), m4);
        float e[NT_];
#pragma unroll
        for (int i = 0; i < NT_; i++) e[i] = __expf(v[i] - m);
        float s0 = (e[0] + e[1]) + (e[2] + e[3]);
        float s1 = (e[4] + e[5]) + (e[6] + e[7]);
        float s2 = (e[8] + e[9]) + (e[10] + e[11]);
        float s = (s0 + s1) + (s2 + e[12]);
        float an = m + __logf(s) + ft;
        if (valid) alpha = an;
    }
    float v = valid ? (alpha + tr[STOP_ * NT_ + jj]) : -1e30f;
    float mm = v;
#pragma unroll
    for (int off = 16; off; off >>= 1) mm = fmaxf(mm, __shfl_xor_sync(0xffffffffu, mm, off));
    float se = __expf(v - mm);
#pragma unroll
    for (int off = 16; off; off >>= 1) se += __shfl_xor_sync(0xffffffffu, se, off);
    float fwd = mm + __logf(se);

    float gold = 0.f;
    for (int t = lane; t < T_; t += 32) {
        int tg = tags[b * T_ + t];
        int tp = (t == 0) ? START_ : tags[b * T_ + t - 1];
        gold += tr[tg * NT_ + tp] + fb[t * NT_ + tg];
    }
#pragma unroll
    for (int off = 16; off; off >>= 1) gold += __shfl_xor_sync(0xffffffffu, gold, off);
    if (lane == 0) {
        int tlast = tags[b * T_ + T_ - 1];
        gold += tr[STOP_ * NT_ + tlast];
        g_nll[b] = fwd - gold;
    }
}

__global__ void k_reduce(float* __restrict__ out) {
    __shared__ float sm[256];
    int tid = threadIdx.x;
    sm[tid] = g_nll[tid];
    __syncthreads();
    for (int s = 128; s > 0; s >>= 1) {
        if (tid < s) sm[tid] += sm[tid + s];
        __syncthreads();
    }
    if (tid == 0) out[0] = sm[0] * (1.f / (float)B_);
}

extern "C" void kernel_launch(void* const* d_in, const int* in_sizes, int n_in,
                              void* d_out, int out_size) {
    const int*   sentence  = (const int*)d_in[0];
    const int*   seq_len   = (const int*)d_in[1];
    const int*   tags      = (const int*)d_in[2];
    const float* embedding = (const float*)d_in[3];
    const float* W_ih_f    = (const float*)d_in[4];
    const float* W_hh_f    = (const float*)d_in[5];
    const float* b_f       = (const float*)d_in[6];
    const float* W_ih_b    = (const float*)d_in[7];
    const float* W_hh_b    = (const float*)d_in[8];
    const float* b_b       = (const float*)d_in[9];
    const float* W_fc      = (const float*)d_in[10];
    const float* b_fc      = (const float*)d_in[11];
    const float* trans     = (const float*)d_in[12];

    dim3 gk((32 * G4 + 255) / 256, 2);
    k_pack<<<gk, 256>>>(W_hh_f, W_hh_b);
    dim3 gp((V_ + 127) / 128, 4, 2);
    k_proj<<<gp, 256>>>(embedding, W_ih_f, b_f, W_ih_b, b_b);
    dim3 gl(B_ / 4, 2);
    k_lstm<<<gl, 256>>>(sentence, seq_len);
    k_fc<<<(B_ * T_) / 8, 256>>>(W_fc, b_fc);
    k_crf<<<B_ / 8, 256>>>(trans, tags);
    k_reduce<<<1, 256>>>((float*)d_out);
}

// round 5
// speedup vs baseline: 1.7482x; 1.3046x over previous
#include <cuda_runtime.h>
#include <cuda_bf16.h>

#define B_    256
#define T_    192
#define E_    300
#define H_    128
#define G4    512
#define V_    11626
#define NT_   13
#define H2_   256
#define NEGV  (-10000.0f)
#define START_ 0
#define STOP_  10

typedef unsigned long long ull;

// ---- device scratch (allocations are forbidden) ----
__device__ float g_proj[2][(size_t)V_ * G4];
__device__ ull   g_Wpbf[2][32 * G4];            // [k4][g] 4 bf16 packed
__device__ float g_featsF[(size_t)B_ * T_ * NT_];
__device__ float g_featsB[(size_t)B_ * T_ * NT_];
__device__ float g_nll[B_];

__device__ __forceinline__ float sigf(float x) { return 1.f / (1.f + __expf(-x)); }
__device__ __forceinline__ float tanhfast(float x) { return 2.f / (1.f + __expf(-2.f * x)) - 1.f; }

__device__ __forceinline__ void fma2(ull& acc, ull a, ull b) {
    asm("fma.rn.f32x2 %0, %1, %2, %0;" : "+l"(acc) : "l"(a), "l"(b));
}
__device__ __forceinline__ ull dupf(float a) {
    ull r; asm("mov.b64 %0, {%1, %1};" : "=l"(r) : "f"(a)); return r;
}
__device__ __forceinline__ float unpack_sum(ull a) {
    float lo, hi; asm("mov.b64 {%0, %1}, %2;" : "=f"(lo), "=f"(hi) : "l"(a)); return lo + hi;
}
__device__ __forceinline__ void unpack2(ull a, float& lo, float& hi) {
    asm("mov.b64 {%0, %1}, %2;" : "=f"(lo), "=f"(hi) : "l"(a));
}
__device__ __forceinline__ void lds_v2(unsigned addr, ull& x, ull& y) {
    asm("ld.shared.v2.u64 {%0, %1}, [%2];" : "=l"(x), "=l"(y) : "r"(addr));
}
__device__ __forceinline__ void expand_bf4(ull w, ull& p01, ull& p23) {
    unsigned lo = (unsigned)w, hi = (unsigned)(w >> 32);
    unsigned f0 = lo << 16, f1 = lo & 0xFFFF0000u;
    unsigned f2 = hi << 16, f3 = hi & 0xFFFF0000u;
    asm("mov.b64 %0, {%1, %2};" : "=l"(p01) : "r"(f0), "r"(f1));
    asm("mov.b64 %0, {%1, %2};" : "=l"(p23) : "r"(f2), "r"(f3));
}

// ---- pack W_hh -> bf16x4 [k4][g] ----
__global__ void k_pack(const float* __restrict__ Wf, const float* __restrict__ Wb) {
    int d = blockIdx.y;
    const float* W = d ? Wb : Wf;
    int idx = blockIdx.x * 256 + threadIdx.x;
    if (idx < 32 * G4) {
        int k4 = idx >> 9, g = idx & 511;
        ull out = 0;
#pragma unroll
        for (int j = 0; j < 4; j++) {
            __nv_bfloat16 b = __float2bfloat16(W[g * H_ + k4 * 4 + j]);
            unsigned short bits = *(unsigned short*)&b;
            out |= (ull)bits << (16 * j);
        }
        g_Wpbf[d][idx] = out;
    }
}

// ---- proj[d][v][g] = emb[v]·W_ih[g] + b[g] ----
__global__ void __launch_bounds__(256) k_proj(const float* __restrict__ emb,
                       const float* __restrict__ Wf, const float* __restrict__ bf,
                       const float* __restrict__ Wb, const float* __restrict__ bb) {
    int d = blockIdx.z;
    const float* W    = d ? Wb : Wf;
    const float* bias = d ? bb : bf;
    __shared__ __align__(16) float As[8][128];
    __shared__ __align__(16) float Ws[8][128];
    int tid = threadIdx.x;
    int tx = tid & 15, ty = tid >> 4;
    int vm0 = blockIdx.x * 128;
    int gn0 = blockIdx.y * 128;
    int sm = tid & 127, skg = tid >> 7;

    ull acc2[8][4];
#pragma unroll
    for (int i = 0; i < 8; i++)
#pragma unroll
        for (int j = 0; j < 4; j++) acc2[i][j] = 0ull;

    unsigned wsb = (unsigned)__cvta_generic_to_shared(&Ws[0][0]) + tx * 32;

    for (int k0 = 0; k0 < 304; k0 += 8) {
        int e = k0 + skg * 4;
        int v = vm0 + sm;
        float4 av = make_float4(0.f, 0.f, 0.f, 0.f);
        if (v < V_ && e < E_) av = *(const float4*)&emb[(size_t)v * E_ + e];
        As[skg * 4 + 0][sm] = av.x;
        As[skg * 4 + 1][sm] = av.y;
        As[skg * 4 + 2][sm] = av.z;
        As[skg * 4 + 3][sm] = av.w;
        float4 wv = make_float4(0.f, 0.f, 0.f, 0.f);
        if (e < E_) wv = *(const float4*)&W[(size_t)(gn0 + sm) * E_ + e];
        Ws[skg * 4 + 0][sm] = wv.x;
        Ws[skg * 4 + 1][sm] = wv.y;
        Ws[skg * 4 + 2][sm] = wv.z;
        Ws[skg * 4 + 3][sm] = wv.w;
        __syncthreads();
#pragma unroll
        for (int kk = 0; kk < 8; kk++) {
            float4 a0 = *(const float4*)&As[kk][ty * 8];
            float4 a1 = *(const float4*)&As[kk][ty * 8 + 4];
            ull w01, w23, w45, w67;
            lds_v2(wsb + kk * 512, w01, w23);
            lds_v2(wsb + kk * 512 + 16, w45, w67);
            float aa[8] = {a0.x, a0.y, a0.z, a0.w, a1.x, a1.y, a1.z, a1.w};
#pragma unroll
            for (int i = 0; i < 8; i++) {
                ull ai = dupf(aa[i]);
                fma2(acc2[i][0], ai, w01);
                fma2(acc2[i][1], ai, w23);
                fma2(acc2[i][2], ai, w45);
                fma2(acc2[i][3], ai, w67);
            }
        }
        __syncthreads();
    }
    float bv[8];
    {
        float4 b0 = *(const float4*)&bias[gn0 + tx * 8];
        float4 b1 = *(const float4*)&bias[gn0 + tx * 8 + 4];
        bv[0] = b0.x; bv[1] = b0.y; bv[2] = b0.z; bv[3] = b0.w;
        bv[4] = b1.x; bv[5] = b1.y; bv[6] = b1.z; bv[7] = b1.w;
    }
#pragma unroll
    for (int i = 0; i < 8; i++) {
        int v = vm0 + ty * 8 + i;
        if (v < V_) {
            float c[8];
#pragma unroll
            for (int j = 0; j < 4; j++) unpack2(acc2[i][j], c[2 * j], c[2 * j + 1]);
            float* dst = &g_proj[d][(size_t)v * G4 + gn0 + tx * 8];
            *(float4*)dst = make_float4(c[0] + bv[0], c[1] + bv[1], c[2] + bv[2], c[3] + bv[3]);
            *(float4*)(dst + 4) = make_float4(c[4] + bv[4], c[5] + bv[5], c[6] + bv[6], c[7] + bv[7]);
        }
    }
}

// ---- BiLSTM recurrence + fused FC: grid (64,2), 512 threads, 1 gate/thread ----
__global__ void __launch_bounds__(512) k_lstm(const int* __restrict__ sent,
                                              const int* __restrict__ seqlen,
                                              const float* __restrict__ Wfc) {
    const int d  = blockIdx.y;
    const int b0 = blockIdx.x * 4;
    __shared__ __align__(16) float h_s[4][128];
    __shared__ __align__(16) float out_s[4][128];
    __shared__ float4 gbuf4[512];
    __shared__ int toks[4][192];
    __shared__ int len_s[4];
    __shared__ float Wfc_s[NT_][128];   // this direction's half of W_fc

    const int tid = threadIdx.x;
    ((float*)h_s)[tid] = 0.f;
    for (int idx = tid; idx < 4 * T_; idx += 512) {
        int r = idx / T_, t = idx % T_;
        toks[r][t] = sent[(b0 + r) * T_ + t];
    }
    if (tid < 4) {
        int L = seqlen[b0 + tid];
        len_s[tid] = L < 1 ? 1 : (L > T_ ? T_ : L);
    }
    for (int i = tid; i < NT_ * H_; i += 512) {
        int j = i >> 7, k = i & 127;
        Wfc_s[j][k] = Wfc[j * H2_ + d * H_ + k];
    }
    __syncthreads();

    int lenr[4];
#pragma unroll
    for (int r = 0; r < 4; r++) lenr[r] = len_s[r];

    const int g = tid;
    const int pr = tid >> 7;       // pointwise row 0..3
    const int pu = tid & 127;
    const int lenp = len_s[pr];
    float c_reg = 0.f;

    const float* __restrict__ proj = g_proj[d];
    const ull* __restrict__ Wp = g_Wpbf[d] + g;
    const unsigned hb = (unsigned)__cvta_generic_to_shared(&h_s[0][0]);
    float* __restrict__ featsD = d ? g_featsB : g_featsF;

    const int w = tid >> 5, lane = tid & 31;
    const int er = w & 3;                       // epilogue row for warps 0..7
    const int ej0 = (w < 4) ? 0 : 7;
    const int ejn = (w < 4) ? 7 : 6;
    const int elen = len_s[er];

    for (int t = 0; t < T_; t++) {
        float pa[4];
#pragma unroll
        for (int r = 0; r < 4; r++) {
            int L = lenr[r];
            bool m = t < L;
            int tt = (d == 0) ? t : (m ? (L - 1 - t) : t);
            int tok = toks[r][tt];
            pa[r] = __ldcg(&proj[(size_t)tok * G4 + g]);
        }
        ull a0 = 0, a1 = 0, a2 = 0, a3 = 0;
        ull w_nxt = Wp[0];
#pragma unroll 4
        for (int k4 = 0; k4 < 32; k4++) {
            ull w_cur = w_nxt;
            if (k4 < 31) w_nxt = Wp[(k4 + 1) * G4];
            ull w01, w23;
            expand_bf4(w_cur, w01, w23);
            unsigned ha = hb + k4 * 16;
            ull h01, h23;
            lds_v2(ha, h01, h23);
            fma2(a0, h01, w01); fma2(a0, h23, w23);
            lds_v2(ha + 512, h01, h23);
            fma2(a1, h01, w01); fma2(a1, h23, w23);
            lds_v2(ha + 1024, h01, h23);
            fma2(a2, h01, w01); fma2(a2, h23, w23);
            lds_v2(ha + 1536, h01, h23);
            fma2(a3, h01, w01); fma2(a3, h23, w23);
        }
        gbuf4[g] = make_float4(pa[0] + unpack_sum(a0), pa[1] + unpack_sum(a1),
                               pa[2] + unpack_sum(a2), pa[3] + unpack_sum(a3));
        __syncthreads();

        // pointwise: one thread per (row, unit)
        {
            const float* gb = (const float*)gbuf4;
            float xi = gb[pu * 4 + pr];
            float xf = gb[(pu + 128) * 4 + pr];
            float xg = gb[(pu + 256) * 4 + pr];
            float xo = gb[(pu + 384) * 4 + pr];
            float si = sigf(xi), sf = sigf(xf), so = sigf(xo);
            float tg = tanhfast(xg);
            float cn = sf * c_reg + si * tg;
            float hn = so * tanhfast(cn);
            bool m = t < lenp;
            float hold = h_s[pr][pu];
            c_reg = m ? cn : c_reg;
            h_s[pr][pu] = m ? hn : hold;
            out_s[pr][pu] = m ? hn : 0.f;
        }
        __syncthreads();

        // fused FC epilogue: warps 0..7 compute feats contribution for this dir
        if (w < 8) {
            float h0 = out_s[er][lane];
            float h1 = out_s[er][lane + 32];
            float h2 = out_s[er][lane + 64];
            float h3 = out_s[er][lane + 96];
            bool m = t < elen;
            int outpos = (d == 0) ? t : (m ? (elen - 1 - t) : t);
            float* dst = &featsD[((size_t)(b0 + er) * T_ + outpos) * NT_];
#pragma unroll
            for (int jj = 0; jj < 7; jj++) {
                if (jj >= ejn) break;
                int j = ej0 + jj;
                float s = h0 * Wfc_s[j][lane] + h1 * Wfc_s[j][lane + 32]
                        + h2 * Wfc_s[j][lane + 64] + h3 * Wfc_s[j][lane + 96];
#pragma unroll
                for (int off = 16; off; off >>= 1) s += __shfl_xor_sync(0xffffffffu, s, off);
                if (lane == 0) dst[j] = s;
            }
        }
    }
}

// ---- CRF (reads featsF + featsB + bias) ----
__global__ void __launch_bounds__(256) k_crf(const float* __restrict__ trans,
                                             const int* __restrict__ tags,
                                             const float* __restrict__ bfc) {
    __shared__ float tr[NT_ * NT_];
    __shared__ float bsh[16];
    int tid = threadIdx.x;
    if (tid < NT_ * NT_) tr[tid] = trans[tid];
    if (tid < NT_) bsh[tid] = bfc[tid];
    __syncthreads();
    int warp = tid >> 5, lane = tid & 31;
    int b = blockIdx.x * 8 + warp;
    bool valid = lane < NT_;
    int jj = valid ? lane : 0;
    float trr[NT_];
#pragma unroll
    for (int i = 0; i < NT_; i++) trr[i] = tr[jj * NT_ + i];
    float bj = bsh[jj];
    float alpha = valid ? ((jj == START_) ? 0.f : NEGV) : -1e30f;
    const float* __restrict__ fF = &g_featsF[(size_t)b * T_ * NT_];
    const float* __restrict__ fB = &g_featsB[(size_t)b * T_ * NT_];

    for (int t = 0; t < T_; t++) {
        float ft = valid ? (fF[t * NT_ + jj] + fB[t * NT_ + jj] + bj) : 0.f;
        float v[NT_];
#pragma unroll
        for (int i = 0; i < NT_; i++)
            v[i] = __shfl_sync(0xffffffffu, alpha, i) + trr[i];
        float m0 = fmaxf(v[0], v[1]),  m1 = fmaxf(v[2], v[3]);
        float m2 = fmaxf(v[4], v[5]),  m3 = fmaxf(v[6], v[7]);
        float m4 = fmaxf(v[8], v[9]),  m5 = fmaxf(v[10], v[11]);
        m0 = fmaxf(m0, m1); m2 = fmaxf(m2, m3); m4 = fmaxf(m4, fmaxf(m5, v[12]));
        float m = fmaxf(fmaxf(m0, m2), m4);
        float e[NT_];
#pragma unroll
        for (int i = 0; i < NT_; i++) e[i] = __expf(v[i] - m);
        float s0 = (e[0] + e[1]) + (e[2] + e[3]);
        float s1 = (e[4] + e[5]) + (e[6] + e[7]);
        float s2 = (e[8] + e[9]) + (e[10] + e[11]);
        float s = (s0 + s1) + (s2 + e[12]);
        float an = m + __logf(s) + ft;
        if (valid) alpha = an;
    }
    float v = valid ? (alpha + tr[STOP_ * NT_ + jj]) : -1e30f;
    float mm = v;
#pragma unroll
    for (int off = 16; off; off >>= 1) mm = fmaxf(mm, __shfl_xor_sync(0xffffffffu, mm, off));
    float se = __expf(v - mm);
#pragma unroll
    for (int off = 16; off; off >>= 1) se += __shfl_xor_sync(0xffffffffu, se, off);
    float fwd = mm + __logf(se);

    float gold = 0.f;
    for (int t = lane; t < T_; t += 32) {
        int tg = tags[b * T_ + t];
        int tp = (t == 0) ? START_ : tags[b * T_ + t - 1];
        gold += tr[tg * NT_ + tp] + fF[t * NT_ + tg] + fB[t * NT_ + tg] + bsh[tg];
    }
#pragma unroll
    for (int off = 16; off; off >>= 1) gold += __shfl_xor_sync(0xffffffffu, gold, off);
    if (lane == 0) {
        int tlast = tags[b * T_ + T_ - 1];
        gold += tr[STOP_ * NT_ + tlast];
        g_nll[b] = fwd - gold;
    }
}

__global__ void k_reduce(float* __restrict__ out) {
    __shared__ float sm[256];
    int tid = threadIdx.x;
    sm[tid] = g_nll[tid];
    __syncthreads();
    for (int s = 128; s > 0; s >>= 1) {
        if (tid < s) sm[tid] += sm[tid + s];
        __syncthreads();
    }
    if (tid == 0) out[0] = sm[0] * (1.f / (float)B_);
}

extern "C" void kernel_launch(void* const* d_in, const int* in_sizes, int n_in,
                              void* d_out, int out_size) {
    const int*   sentence  = (const int*)d_in[0];
    const int*   seq_len   = (const int*)d_in[1];
    const int*   tags      = (const int*)d_in[2];
    const float* embedding = (const float*)d_in[3];
    const float* W_ih_f    = (const float*)d_in[4];
    const float* W_hh_f    = (const float*)d_in[5];
    const float* b_f       = (const float*)d_in[6];
    const float* W_ih_b    = (const float*)d_in[7];
    const float* W_hh_b    = (const float*)d_in[8];
    const float* b_b       = (const float*)d_in[9];
    const float* W_fc      = (const float*)d_in[10];
    const float* b_fc      = (const float*)d_in[11];
    const float* trans     = (const float*)d_in[12];

    dim3 gk((32 * G4 + 255) / 256, 2);
    k_pack<<<gk, 256>>>(W_hh_f, W_hh_b);
    dim3 gp((V_ + 127) / 128, 4, 2);
    k_proj<<<gp, 256>>>(embedding, W_ih_f, b_f, W_ih_b, b_b);
    dim3 gl(B_ / 4, 2);
    k_lstm<<<gl, 512>>>(sentence, seq_len, W_fc);
    k_crf<<<B_ / 8, 256>>>(trans, tags, b_fc);
    k_reduce<<<1, 256>>>((float*)d_out);
}